// round 5
// baseline (speedup 1.0000x reference)
#include <cuda_runtime.h>
#include <cstdint>

#define N_Q 4096
#define QTR 1024
#define NTHREADS 1024
#define CLUSTER 4
#define EVAL_PT_SCORE 0.05f
#define D2_THRESH 25.0f   // 5.0^2
#define NBR_CAP 6
#define OVF 255
#define HCAP 2560         // halo-region point capacity (expected ~1150)
#define WCAP 2048         // worklist capacity (expected ~900)

// smem map (bytes, 8B-aligned groups first):
// hkey u64[2560] 20480 | ixy f2[4096] 32768 | hxy f2[2560] 20480 | iscore f32[4096] 16384
// bstart[4097] 16388 | bcur[4096] 16384 | hstart[2049] 8196 | hcur[2048] 8192
// warpsum[64] 256 | bpt u16[4096] 8192 | hidx u16[2560] 5120 | hcell u16[2560] 5120
// wl u16[2048] 4096 | nbr u16[2048*6] 24576 | stat u8[4096] 4096 | nbrcnt u8[2048] 2048
#define SMEM_BYTES 192776

__device__ __forceinline__ uint32_t smem_u32(const void* p) {
    uint32_t a;
    asm("{ .reg .u64 t; cvta.to.shared.u64 t, %1; cvt.u32.u64 %0, t; }"
        : "=r"(a) : "l"(p));
    return a;
}
__device__ __forceinline__ uint32_t mapa_rank(uint32_t addr, uint32_t r) {
    uint32_t o;
    asm("mapa.shared::cluster.u32 %0, %1, %2;" : "=r"(o) : "r"(addr), "r"(r));
    return o;
}
__device__ __forceinline__ void st_cl_u8(uint32_t addr, uint32_t v) {
    asm volatile("st.shared::cluster.u8 [%0], %1;" :: "r"(addr), "r"(v) : "memory");
}
__device__ __forceinline__ void st_cl_u32(uint32_t addr, uint32_t v) {
    asm volatile("st.shared::cluster.u32 [%0], %1;" :: "r"(addr), "r"(v) : "memory");
}
__device__ __forceinline__ void st_cl_f32(uint32_t addr, float v) {
    asm volatile("st.shared::cluster.f32 [%0], %1;" :: "r"(addr), "f"(v) : "memory");
}
__device__ __forceinline__ void st_cl_v2f32(uint32_t addr, float a, float b) {
    asm volatile("st.shared::cluster.v2.f32 [%0], {%1,%2};"
                 :: "r"(addr), "f"(a), "f"(b) : "memory");
}
#define CLUSTER_SYNC() do { \
    asm volatile("barrier.cluster.arrive.aligned;" ::: "memory"); \
    asm volatile("barrier.cluster.wait.aligned;" ::: "memory"); } while (0)

__device__ __forceinline__ int warp_incl_scan(int v) {
    int lane = threadIdx.x & 31;
    #pragma unroll
    for (int o = 1; o < 32; o <<= 1) {
        int n = __shfl_up_sync(0xffffffffu, v, o);
        if (lane >= o) v += n;
    }
    return v;
}

__device__ __forceinline__ unsigned long long mk_key(float s, int i) {
    bool valid = (s >= EVAL_PT_SCORE);
    unsigned int fb = __float_as_uint(s);
    return valid
        ? ((((unsigned long long)fb) << 32) | (unsigned int)(N_Q - 1 - i))
        : (unsigned long long)(unsigned int)(N_Q - 1 - i);
}

__global__ void __launch_bounds__(NTHREADS, 1) __cluster_dims__(CLUSTER, 1, 1)
nms_kernel(const float* __restrict__ logits,
           const float* __restrict__ boxes,
           const float* __restrict__ ts,
           float* __restrict__ out) {
    const int cls = blockIdx.x / CLUSTER;   // 0 = end, 1 = junction
    const int rank = blockIdx.x & (CLUSTER - 1);
    const int tid = threadIdx.x;
    const int lane = tid & 31;
    const int wid = tid >> 5;
    const int rbase = 16 * rank - 1;        // halo local row 0 = cell row rbase

    extern __shared__ unsigned char sm[];
    unsigned long long* hkey = (unsigned long long*)sm;          // [HCAP]
    float2* ixy = (float2*)(hkey + HCAP);                        // [N_Q]
    float2* hxy = ixy + N_Q;                                     // [HCAP]
    float* iscore = (float*)(hxy + HCAP);                        // [N_Q]
    int* bstart = (int*)(iscore + N_Q);                          // [N_Q+1]
    int* bcur   = bstart + (N_Q + 1);                            // [N_Q]
    int* hstart = bcur + N_Q;                                    // [2049]
    int* hcur   = hstart + 2049;                                 // [2048]
    int* warpsum = hcur + 2048;                                  // [64]
    unsigned short* bpt   = (unsigned short*)(warpsum + 64);     // [N_Q]
    unsigned short* hidx  = bpt + N_Q;                           // [HCAP]
    unsigned short* hcell = hidx + HCAP;                         // [HCAP]
    unsigned short* wl    = hcell + HCAP;                        // [WCAP]
    unsigned short* nbr   = wl + WCAP;                           // [WCAP*NBR_CAP]
    unsigned char* stat   = (unsigned char*)(nbr + WCAP * NBR_CAP); // [N_Q]
    unsigned char* nbrcnt = stat + N_Q;                          // [WCAP]
    __shared__ int s_cnt[CLUSTER];
    __shared__ int s_wl, s_chg, s_pend;

    const float tw = ts[0], th = ts[1];

    // ---------- phase A: index-quarter softmax + broadcast (s,x,y) ----------
    {
        int i = rank * QTR + tid;
        float l0 = logits[3 * i + 0];
        float l1 = logits[3 * i + 1];
        float l2 = logits[3 * i + 2];
        float m = fmaxf(l0, fmaxf(l1, l2));
        float e0 = expf(l0 - m), e1 = expf(l1 - m), e2 = expf(l2 - m);
        float inv = 1.0f / (e0 + e1 + e2);
        float p0 = e0 * inv, p1 = e1 * inv, p2 = e2 * inv;
        float x = boxes[2 * i + 0] * tw;
        float y = boxes[2 * i + 1] * th;
        float s = (cls == 0) ? p0 : p1;
        iscore[i] = s;
        ixy[i] = make_float2(x, y);
        uint32_t a_is = smem_u32(&iscore[i]);
        uint32_t a_xy = smem_u32(&ixy[i]);
        #pragma unroll
        for (int r = 0; r < CLUSTER; r++) {
            if (r == rank) continue;
            st_cl_f32(mapa_rank(a_is, r), s);
            st_cl_v2f32(mapa_rank(a_xy, r), x, y);
        }
        if (cls == 0) {
            out[5 * i + 0] = 1.0f - p2;
            out[5 * i + 1] = x;
            out[5 * i + 2] = y;
            out[5 * i + 3] = 0.0f;
        } else {
            out[5 * i + 4] = 0.0f;
        }
    }
    // zero histograms
    for (int c = tid; c < N_Q + 1; c += NTHREADS) bstart[c] = 0;
    for (int c = tid; c < 2049; c += NTHREADS) hstart[c] = 0;
    if (tid == 0) s_wl = 0;
    CLUSTER_SYNC();   // peers' (s,x,y) visible; also block barrier

    // ---------- phase B: classify all 4096 points; histograms ----------
    float rsc[4], rxx[4], ryy[4];
    int rbk[4], rlc[4];   // rlc = local halo cell or -1
    #pragma unroll
    for (int k = 0; k < 4; k++) {
        int j = 4 * tid + k;
        float s = iscore[j];
        float2 p = ixy[j];
        rsc[k] = s; rxx[k] = p.x; ryy[k] = p.y;
        bool valid = (s >= EVAL_PT_SCORE);
        stat[j] = valid ? (unsigned char)0 : (unsigned char)2;
        int cx = min(63, max(0, (int)(p.x * 0.125f)));
        int cy = min(63, max(0, (int)(p.y * 0.125f)));
        int lr = cy - rbase;
        rlc[k] = (lr >= 0 && lr < 18) ? (lr * 64 + cx) : -1;
        rbk[k] = min(4095, (int)(s * 4096.0f));
        if (valid) atomicAdd(&bstart[rbk[k]], 1);
        if (rlc[k] >= 0) atomicAdd(&hstart[rlc[k]], 1);
    }
    __syncthreads();

    // ---------- scans: bucket (4096, 4/thread) then halo cells (2048, 2/thread) ----------
    {
        int g0 = bstart[4 * tid], g1 = bstart[4 * tid + 1];
        int g2 = bstart[4 * tid + 2], g3 = bstart[4 * tid + 3];
        int lb = g0 + g1 + g2 + g3;
        int ib = warp_incl_scan(lb);
        if (lane == 31) warpsum[wid] = ib;
        __syncthreads();
        if (wid == 0) warpsum[lane] = warp_incl_scan(warpsum[lane]);
        __syncthreads();
        int baseb = ib - lb + (wid ? warpsum[wid - 1] : 0);
        bstart[4 * tid] = baseb;                     bcur[4 * tid] = baseb;
        bstart[4 * tid + 1] = baseb + g0;            bcur[4 * tid + 1] = baseb + g0;
        bstart[4 * tid + 2] = baseb + g0 + g1;       bcur[4 * tid + 2] = baseb + g0 + g1;
        bstart[4 * tid + 3] = baseb + g0 + g1 + g2;  bcur[4 * tid + 3] = baseb + g0 + g1 + g2;
        if (tid == NTHREADS - 1) bstart[N_Q] = baseb + lb;
    }
    __syncthreads();
    {
        int a = hstart[2 * tid], b = hstart[2 * tid + 1];
        int l = a + b;
        int il = warp_incl_scan(l);
        if (lane == 31) warpsum[wid] = il;
        __syncthreads();
        if (wid == 0) warpsum[lane] = warp_incl_scan(warpsum[lane]);
        __syncthreads();
        int base = il - l + (wid ? warpsum[wid - 1] : 0);
        hstart[2 * tid] = base;      hcur[2 * tid] = base;
        hstart[2 * tid + 1] = base + a; hcur[2 * tid + 1] = base + a;
        if (tid == NTHREADS - 1) hstart[2048] = base + l;
    }
    __syncthreads();
    const int htotal = hstart[2048];

    // ---------- phase C: scatter halo points (cell order) + bucket list ----------
    #pragma unroll
    for (int k = 0; k < 4; k++) {
        int j = 4 * tid + k;
        if (rlc[k] >= 0) {
            int pos = atomicAdd(&hcur[rlc[k]], 1);
            hkey[pos] = mk_key(rsc[k], j);
            hxy[pos] = make_float2(rxx[k], ryy[k]);
            hidx[pos] = (unsigned short)j;
            hcell[pos] = (unsigned short)rlc[k];
        }
        if (rsc[k] >= EVAL_PT_SCORE) {
            int bp = atomicAdd(&bcur[rbk[k]], 1);
            bpt[bp] = (unsigned short)j;
        }
    }
    __syncthreads();

    // ---------- edge build for OWNED points (cy>>4 == rank) ----------
    for (int p = tid; p < htotal; p += NTHREADS) {
        unsigned long long kj = hkey[p];
        if (!(kj >> 32)) continue;                 // invalid
        int lc = hcell[p];
        int cx = lc & 63, lr = lc >> 6;
        int cy = lr + rbase;
        if ((cy >> 4) != rank) continue;           // halo-only point
        float2 pj = hxy[p];
        int x0 = max(cx - 1, 0), x1 = min(cx + 1, 63);
        unsigned short tmp[NBR_CAP];
        int cnt = 0;
        #pragma unroll
        for (int rr = lr - 1; rr <= lr + 1; rr++) {   // rows 0..17 always in-range for owned
            int rs = hstart[rr * 64 + x0];
            int re = hstart[rr * 64 + x1 + 1];
            for (int q = rs; q < re; q++) {
                unsigned long long ki = hkey[q];
                if (ki <= kj) continue;            // lower rank / invalid / self
                float2 pi = hxy[q];
                float dx = pi.x - pj.x, dy = pi.y - pj.y;
                if (dx * dx + dy * dy < D2_THRESH) {
                    if (cnt < NBR_CAP) tmp[cnt] = hidx[q];
                    cnt++;
                }
            }
        }
        int i = hidx[p];
        if (cnt == 0) {
            stat[i] = 1;                           // no higher-ranked neighbor
        } else {
            int w = atomicAdd(&s_wl, 1);
            wl[w] = (unsigned short)p;
            nbrcnt[w] = (cnt > NBR_CAP) ? (unsigned char)OVF : (unsigned char)cnt;
            #pragma unroll
            for (int k = 0; k < NBR_CAP; k++)
                if (k < cnt) nbr[w * NBR_CAP + k] = tmp[k];
        }
    }
    __syncthreads();
    const int nwl = s_wl;

    // all CTAs past stat-init before any remote stat store
    CLUSTER_SYNC();

    // initial exchange of edge-build results (owned stats)
    for (int p = tid; p < htotal; p += NTHREADS) {
        int lc = hcell[p];
        int cy = (lc >> 6) + rbase;
        if ((cy >> 4) != rank) continue;
        int i = hidx[p];
        unsigned int v = stat[i];
        uint32_t a = smem_u32(&stat[i]);
        #pragma unroll
        for (int r = 0; r < CLUSTER; r++)
            if (r != rank) st_cl_u8(mapa_rank(a, r), v);
    }
    CLUSTER_SYNC();

    // ---------- outer rounds: local fixed point + stat exchange ----------
    while (true) {
        // inner local fixed point (cheap __syncthreads rounds)
        int pend;
        while (true) {
            if (tid == 0) { s_chg = 0; s_pend = 0; }
            __syncthreads();
            int lchg = 0, lpend = 0;
            for (int w = tid; w < nwl; w += NTHREADS) {
                int p = wl[w];
                int i = hidx[p];
                if (stat[i] != 0) continue;
                int c = nbrcnt[w];
                bool sup = false, pd = false;
                if (c != OVF) {
                    #pragma unroll 1
                    for (int k = 0; k < c; k++) {
                        unsigned char st = stat[nbr[w * NBR_CAP + k]];
                        if (st == 1) { sup = true; break; }
                        if (st == 0) pd = true;
                    }
                } else {
                    unsigned long long kj = hkey[p];
                    float2 pj = hxy[p];
                    int lc = hcell[p];
                    int cx = lc & 63, lr = lc >> 6;
                    int x0 = max(cx - 1, 0), x1 = min(cx + 1, 63);
                    for (int rr = lr - 1; rr <= lr + 1 && !sup; rr++) {
                        int rs = hstart[rr * 64 + x0];
                        int re = hstart[rr * 64 + x1 + 1];
                        for (int q = rs; q < re; q++) {
                            unsigned long long ki = hkey[q];
                            if (ki <= kj) continue;
                            float2 pi = hxy[q];
                            float dx = pi.x - pj.x, dy = pi.y - pj.y;
                            if (dx * dx + dy * dy < D2_THRESH) {
                                unsigned char st = stat[hidx[q]];
                                if (st == 1) { sup = true; break; }
                                if (st == 0) pd = true;
                            }
                        }
                    }
                }
                if (sup)      { stat[i] = 2; lchg++; }
                else if (!pd) { stat[i] = 1; lchg++; }
                else          lpend++;
            }
            if (lchg) atomicAdd(&s_chg, lchg);
            if (lpend) atomicAdd(&s_pend, lpend);
            __syncthreads();
            if (s_chg == 0) { pend = s_pend; break; }
        }
        // broadcast owned stats + pending count
        for (int p = tid; p < htotal; p += NTHREADS) {
            int lc = hcell[p];
            int cy = (lc >> 6) + rbase;
            if ((cy >> 4) != rank) continue;
            int i = hidx[p];
            unsigned int v = stat[i];
            uint32_t a = smem_u32(&stat[i]);
            #pragma unroll
            for (int r = 0; r < CLUSTER; r++)
                if (r != rank) st_cl_u8(mapa_rank(a, r), v);
        }
        if (tid == 0) {
            s_cnt[rank] = pend;
            uint32_t a = smem_u32(&s_cnt[rank]);
            #pragma unroll
            for (int r = 0; r < CLUSTER; r++)
                if (r != rank) st_cl_u32(mapa_rank(a, r), (unsigned int)pend);
        }
        CLUSTER_SYNC();
        if (s_cnt[0] + s_cnt[1] + s_cnt[2] + s_cnt[3] == 0) break;
    }

    // ---------- rank MY index-quarter's retained, scatter to output ----------
    {
        const int nvalid = bstart[N_Q];
        int i = rank * QTR + tid;
        if (stat[i] == 1) {
            float s = iscore[i];
            unsigned long long kj = mk_key(s, i);
            int b = min(4095, (int)(s * 4096.0f));
            int r = nvalid - bstart[b + 1];
            int e = bstart[b + 1];
            for (int q = bstart[b]; q < e; q++) {
                int idx2 = bpt[q];
                if (mk_key(iscore[idx2], idx2) > kj) r++;
            }
            out[5 * r + 3 + cls] = s;
        }
    }
}

extern "C" void kernel_launch(void* const* d_in, const int* in_sizes, int n_in,
                              void* d_out, int out_size) {
    const float* logits = (const float*)d_in[0];   // [1,4096,3]
    const float* boxes  = (const float*)d_in[1];   // [1,4096,2]
    // d_in[2] = pred_gids (unused by reference)
    const float* ts     = (const float*)d_in[3];   // [1,2] = (w,h)
    float* out = (float*)d_out;                    // [1,4096,5]

    cudaFuncSetAttribute(nms_kernel,
                         cudaFuncAttributeMaxDynamicSharedMemorySize, SMEM_BYTES);
    nms_kernel<<<2 * CLUSTER, NTHREADS, SMEM_BYTES>>>(logits, boxes, ts, out);
}

// round 6
// speedup vs baseline: 1.3556x; 1.3556x over previous
#include <cuda_runtime.h>
#include <cstdint>

#define N_Q 4096
#define NTHREADS 1024
#define CLUSTER 4
#define EVAL_PT_SCORE 0.05f
#define D2_THRESH 25.0f   // 5.0^2
#define NBR_CAP 6
#define OVF 255
#define HCAP 2560         // stripe+halo point capacity (expected ~1150)
#define WCAP 2048         // worklist capacity (expected ~460)
#define NBUCK 1024
#define NCELLS 2048       // padded power-of-2 (actual 18*64=1152)

// smem (bytes):
// uint4 hrec[2560] 40960 | u64 skey[4096] 32768
// int bstart[1025] 4100 | int bcur[1024] 4096 | int hstart[2049] 8196 | int hcur[2048] 8192
// int warpsum[64] 256 | u16 bpt[4096] 8192 | u16 hidx[2560] 5120 | u16 hcell[2560] 5120
// u16 wl[2048] 4096 | u16 nbr[2048*6] 24576 | u8 stat[4096] 4096 | u8 nbrcnt[2048] 2048
#define SMEM_BYTES 151816

__device__ __forceinline__ uint32_t smem_u32(const void* p) {
    uint32_t a;
    asm("{ .reg .u64 t; cvta.to.shared.u64 t, %1; cvt.u32.u64 %0, t; }"
        : "=r"(a) : "l"(p));
    return a;
}
__device__ __forceinline__ uint32_t mapa_rank(uint32_t addr, uint32_t r) {
    uint32_t o;
    asm("mapa.shared::cluster.u32 %0, %1, %2;" : "=r"(o) : "r"(addr), "r"(r));
    return o;
}
__device__ __forceinline__ void st_cl_u8(uint32_t addr, uint32_t v) {
    asm volatile("st.shared::cluster.u8 [%0], %1;" :: "r"(addr), "r"(v) : "memory");
}
__device__ __forceinline__ void st_cl_u32(uint32_t addr, uint32_t v) {
    asm volatile("st.shared::cluster.u32 [%0], %1;" :: "r"(addr), "r"(v) : "memory");
}
#define CLUSTER_SYNC() do { \
    asm volatile("barrier.cluster.arrive.aligned;" ::: "memory"); \
    asm volatile("barrier.cluster.wait.aligned;" ::: "memory"); } while (0)

__device__ __forceinline__ int warp_incl_scan(int v) {
    int lane = threadIdx.x & 31;
    #pragma unroll
    for (int o = 1; o < 32; o <<= 1) {
        int n = __shfl_up_sync(0xffffffffu, v, o);
        if (lane >= o) v += n;
    }
    return v;
}

__device__ __forceinline__ unsigned long long mk_key(float s, int i) {
    bool valid = (s >= EVAL_PT_SCORE);
    unsigned int fb = __float_as_uint(s);
    return valid
        ? ((((unsigned long long)fb) << 32) | (unsigned int)(N_Q - 1 - i))
        : (unsigned long long)(unsigned int)(N_Q - 1 - i);
}

__global__ void __launch_bounds__(NTHREADS, 1) __cluster_dims__(CLUSTER, 1, 1)
nms_kernel(const float* __restrict__ logits,
           const float* __restrict__ boxes,
           const float* __restrict__ ts,
           float* __restrict__ out) {
    const int cls = blockIdx.x / CLUSTER;     // 0 = end, 1 = junction
    const int rank = blockIdx.x & (CLUSTER - 1);
    const int tid = threadIdx.x;
    const int lane = tid & 31;
    const int wid = tid >> 5;
    const int rbase = 16 * rank - 1;          // stripe-local row 0 = cell row rbase

    extern __shared__ unsigned char sm[];
    uint4* hrec = (uint4*)sm;                                   // [HCAP]
    unsigned long long* skey = (unsigned long long*)(hrec + HCAP); // [N_Q]
    int* bstart = (int*)(skey + N_Q);                           // [NBUCK+1]
    int* bcur   = bstart + (NBUCK + 1);                         // [NBUCK]
    int* hstart = bcur + NBUCK;                                 // [NCELLS+1]
    int* hcur   = hstart + (NCELLS + 1);                        // [NCELLS]
    int* warpsum = hcur + NCELLS;                               // [64]
    unsigned short* bpt   = (unsigned short*)(warpsum + 64);    // [N_Q]
    unsigned short* hidx  = bpt + N_Q;                          // [HCAP]
    unsigned short* hcell = hidx + HCAP;                        // [HCAP]
    unsigned short* wl    = hcell + HCAP;                       // [WCAP]
    unsigned short* nbr   = wl + WCAP;                          // [WCAP*NBR_CAP]
    unsigned char* stat   = (unsigned char*)(nbr + WCAP * NBR_CAP); // [N_Q]
    unsigned char* nbrcnt = stat + N_Q;                         // [WCAP]
    __shared__ int s_cnt[CLUSTER];
    __shared__ int s_wl, s_chg, s_pend;

    const float tw = ts[0], th = ts[1];

    // ---- zero histograms ----
    for (int c = tid; c < NBUCK + 1; c += NTHREADS) bstart[c] = 0;
    for (int c = tid; c < NCELLS + 1; c += NTHREADS) hstart[c] = 0;
    if (tid == 0) s_wl = 0;
    __syncthreads();

    // ---- phase A: duplicated softmax over ALL 4096; keys, stat, hist ----
    unsigned long long rkey[4];
    float rx[4], ry[4];
    int rb[4], rlc[4];
    #pragma unroll
    for (int k = 0; k < 4; k++) {
        int j = k * NTHREADS + tid;               // coalesced; quarter k == rank
        float l0 = logits[3 * j + 0];
        float l1 = logits[3 * j + 1];
        float l2 = logits[3 * j + 2];
        float m = fmaxf(l0, fmaxf(l1, l2));
        float e0 = expf(l0 - m), e1 = expf(l1 - m), e2 = expf(l2 - m);
        float inv = 1.0f / (e0 + e1 + e2);
        float p0 = e0 * inv, p1 = e1 * inv, p2 = e2 * inv;
        float x = boxes[2 * j + 0] * tw;
        float y = boxes[2 * j + 1] * th;
        float s = (cls == 0) ? p0 : p1;
        bool valid = (s >= EVAL_PT_SCORE);
        unsigned long long key = mk_key(s, j);
        rkey[k] = key; rx[k] = x; ry[k] = y;
        skey[j] = key;
        stat[j] = valid ? (unsigned char)0 : (unsigned char)2;
        rb[k] = min(NBUCK - 1, (int)(s * (float)NBUCK));
        if (valid) atomicAdd(&bstart[rb[k]], 1);
        int cx = min(63, max(0, (int)(x * 0.125f)));
        int cy = min(63, max(0, (int)(y * 0.125f)));
        int lr = cy - rbase;
        rlc[k] = (lr >= 0 && lr < 18) ? (lr * 64 + cx) : -1;
        if (rlc[k] >= 0) atomicAdd(&hstart[rlc[k]], 1);
        if (k == rank) {                          // my index quarter's static outputs
            if (cls == 0) {
                out[5 * j + 0] = 1.0f - p2;
                out[5 * j + 1] = x;
                out[5 * j + 2] = y;
                out[5 * j + 3] = 0.0f;
            } else {
                out[5 * j + 4] = 0.0f;
            }
        }
    }
    __syncthreads();

    // ---- bucket exclusive scan (1/thread) ----
    {
        int v = bstart[tid];
        int iv = warp_incl_scan(v);
        if (lane == 31) warpsum[wid] = iv;
        __syncthreads();
        if (wid == 0) warpsum[lane] = warp_incl_scan(warpsum[lane]);
        __syncthreads();
        int ex = iv - v + (wid ? warpsum[wid - 1] : 0);
        bstart[tid] = ex; bcur[tid] = ex;
        if (tid == NTHREADS - 1) bstart[NBUCK] = ex + v;
    }
    __syncthreads();
    // ---- cell exclusive scan (2/thread) ----
    {
        int a = hstart[2 * tid], b = hstart[2 * tid + 1];
        int l = a + b;
        int il = warp_incl_scan(l);
        if (lane == 31) warpsum[wid] = il;
        __syncthreads();
        if (wid == 0) warpsum[lane] = warp_incl_scan(warpsum[lane]);
        __syncthreads();
        int base = il - l + (wid ? warpsum[wid - 1] : 0);
        hstart[2 * tid] = base;      hcur[2 * tid] = base;
        hstart[2 * tid + 1] = base + a; hcur[2 * tid + 1] = base + a;
        if (tid == NTHREADS - 1) hstart[NCELLS] = base + l;
    }
    __syncthreads();
    const int htotal = hstart[NCELLS];

    // ---- scatter: bucket list (valid) + stripe records ----
    #pragma unroll
    for (int k = 0; k < 4; k++) {
        int j = k * NTHREADS + tid;
        if (rkey[k] >> 32) {
            int bp = atomicAdd(&bcur[rb[k]], 1);
            bpt[bp] = (unsigned short)j;
        }
        if (rlc[k] >= 0) {
            int pos = atomicAdd(&hcur[rlc[k]], 1);
            hrec[pos] = make_uint4((unsigned int)rkey[k],
                                   (unsigned int)(rkey[k] >> 32),
                                   __float_as_uint(rx[k]),
                                   __float_as_uint(ry[k]));
            hidx[pos] = (unsigned short)j;
            hcell[pos] = (unsigned short)rlc[k];
        }
    }
    __syncthreads();

    // ---- edge build for OWNED points (local rows 1..16) ----
    for (int p = tid; p < htotal; p += NTHREADS) {
        uint4 R = hrec[p];
        if (R.y == 0) continue;                   // invalid
        int lc = hcell[p];
        int lr = lc >> 6;
        if (lr < 1 || lr > 16) continue;          // halo-only
        unsigned long long kj = ((unsigned long long)R.y << 32) | R.x;
        float xj = __uint_as_float(R.z), yj = __uint_as_float(R.w);
        int cx = lc & 63;
        int x0 = max(cx - 1, 0), x1 = min(cx + 1, 63);
        unsigned short tmp[NBR_CAP];
        int cnt = 0;
        #pragma unroll
        for (int rr = lr - 1; rr <= lr + 1; rr++) {
            int qs = hstart[rr * 64 + x0];
            int qe = hstart[rr * 64 + x1 + 1];
            for (int q = qs; q < qe; q++) {
                uint4 C = hrec[q];
                unsigned long long ki = ((unsigned long long)C.y << 32) | C.x;
                if (ki <= kj) continue;           // lower rank / invalid / self
                float dx = __uint_as_float(C.z) - xj;
                float dy = __uint_as_float(C.w) - yj;
                if (dx * dx + dy * dy < D2_THRESH) {
                    if (cnt < NBR_CAP) tmp[cnt] = hidx[q];
                    cnt++;
                }
            }
        }
        int i = hidx[p];
        if (cnt == 0) {
            stat[i] = 1;
        } else {
            int w = atomicAdd(&s_wl, 1);
            wl[w] = (unsigned short)p;
            nbrcnt[w] = (cnt > NBR_CAP) ? (unsigned char)OVF : (unsigned char)cnt;
            #pragma unroll
            for (int k = 0; k < NBR_CAP; k++)
                if (k < cnt) nbr[w * NBR_CAP + k] = tmp[k];
        }
    }
    __syncthreads();
    const int nwl = s_wl;

    CLUSTER_SYNC();   // stat init complete cluster-wide before any remote store

    // boundary stat send: local row 1 (cy=16r) -> rank-1; row 16 (cy=16r+15) -> rank+1
    #define SEND_BOUNDARY() do {                                              \
        if (rank > 0) {                                                       \
            int qs = hstart[64], qe = hstart[128];                            \
            for (int p = qs + tid; p < qe; p += NTHREADS) {                   \
                int i = hidx[p];                                              \
                st_cl_u8(mapa_rank(smem_u32(&stat[i]), rank - 1), stat[i]);   \
            }                                                                 \
        }                                                                     \
        if (rank < CLUSTER - 1) {                                             \
            int qs = hstart[16 * 64], qe = hstart[17 * 64];                   \
            for (int p = qs + tid; p < qe; p += NTHREADS) {                   \
                int i = hidx[p];                                              \
                st_cl_u8(mapa_rank(smem_u32(&stat[i]), rank + 1), stat[i]);   \
            }                                                                 \
        }                                                                     \
    } while (0)

    SEND_BOUNDARY();
    CLUSTER_SYNC();

    // ---- outer rounds: local fixed point + boundary exchange ----
    while (true) {
        int pend;
        while (true) {
            if (tid == 0) { s_chg = 0; s_pend = 0; }
            __syncthreads();
            int lchg = 0, lpend = 0;
            for (int w = tid; w < nwl; w += NTHREADS) {
                int p = wl[w];
                int i = hidx[p];
                if (stat[i] != 0) continue;
                int c = nbrcnt[w];
                bool sup = false, pd = false;
                if (c != OVF) {
                    #pragma unroll 1
                    for (int k = 0; k < c; k++) {
                        unsigned char st = stat[nbr[w * NBR_CAP + k]];
                        if (st == 1) { sup = true; break; }
                        if (st == 0) pd = true;
                    }
                } else {
                    uint4 R = hrec[p];
                    unsigned long long kj = ((unsigned long long)R.y << 32) | R.x;
                    float xj = __uint_as_float(R.z), yj = __uint_as_float(R.w);
                    int lc = hcell[p];
                    int cx = lc & 63, lr = lc >> 6;
                    int x0 = max(cx - 1, 0), x1 = min(cx + 1, 63);
                    for (int rr = lr - 1; rr <= lr + 1 && !sup; rr++) {
                        int qs = hstart[rr * 64 + x0];
                        int qe = hstart[rr * 64 + x1 + 1];
                        for (int q = qs; q < qe; q++) {
                            uint4 C = hrec[q];
                            unsigned long long ki = ((unsigned long long)C.y << 32) | C.x;
                            if (ki <= kj) continue;
                            float dx = __uint_as_float(C.z) - xj;
                            float dy = __uint_as_float(C.w) - yj;
                            if (dx * dx + dy * dy < D2_THRESH) {
                                unsigned char st = stat[hidx[q]];
                                if (st == 1) { sup = true; break; }
                                if (st == 0) pd = true;
                            }
                        }
                    }
                }
                if (sup)      { stat[i] = 2; lchg++; }
                else if (!pd) { stat[i] = 1; lchg++; }
                else          lpend++;
            }
            if (lchg) atomicAdd(&s_chg, lchg);
            if (lpend) atomicAdd(&s_pend, lpend);
            __syncthreads();
            if (s_chg == 0) { pend = s_pend; break; }
        }
        SEND_BOUNDARY();
        if (tid == 0) {
            s_cnt[rank] = pend;
            uint32_t a = smem_u32(&s_cnt[rank]);
            #pragma unroll
            for (int r = 0; r < CLUSTER; r++)
                if (r != rank) st_cl_u32(mapa_rank(a, r), (unsigned int)pend);
        }
        CLUSTER_SYNC();
        if (s_cnt[0] + s_cnt[1] + s_cnt[2] + s_cnt[3] == 0) break;
    }

    // ---- owner writes outputs for owned retained points ----
    {
        const int nvalid = bstart[NBUCK];
        for (int p = tid; p < htotal; p += NTHREADS) {
            int lc = hcell[p];
            int lr = lc >> 6;
            if (lr < 1 || lr > 16) continue;      // not owned
            int i = hidx[p];
            if (stat[i] != 1) continue;
            uint4 R = hrec[p];
            unsigned long long kj = ((unsigned long long)R.y << 32) | R.x;
            float s = __uint_as_float(R.y);
            int b = min(NBUCK - 1, (int)(s * (float)NBUCK));
            int r = nvalid - bstart[b + 1];
            int e = bstart[b + 1];
            for (int q = bstart[b]; q < e; q++) {
                if (skey[bpt[q]] > kj) r++;
            }
            out[5 * r + 3 + cls] = s;
        }
    }
}

extern "C" void kernel_launch(void* const* d_in, const int* in_sizes, int n_in,
                              void* d_out, int out_size) {
    const float* logits = (const float*)d_in[0];   // [1,4096,3]
    const float* boxes  = (const float*)d_in[1];   // [1,4096,2]
    // d_in[2] = pred_gids (unused by reference)
    const float* ts     = (const float*)d_in[3];   // [1,2] = (w,h)
    float* out = (float*)d_out;                    // [1,4096,5]

    cudaFuncSetAttribute(nms_kernel,
                         cudaFuncAttributeMaxDynamicSharedMemorySize, SMEM_BYTES);
    nms_kernel<<<2 * CLUSTER, NTHREADS, SMEM_BYTES>>>(logits, boxes, ts, out);
}